// round 1
// baseline (speedup 1.0000x reference)
#include <cuda_runtime.h>

// MakeCutouts: 32 cutouts of x[8,3,512,512] fp32, each adaptive-avg-pooled to
// 224x224. Output [32*8, 3, 224, 224] fp32.
//
// Inputs (metadata order): x (f32, 8*3*512*512), sizes (i32,32),
// offsets_y (i32,32), offsets_x (i32,32), [cut_size scalar, unused — constant 224].

#define OUTS   224
#define BATCH  8
#define CHAN   3
#define HW     512
#define CUTN   32

__global__ __launch_bounds__(256)
void makecutouts_kernel(const float* __restrict__ x,
                        const int* __restrict__ sizes,
                        const int* __restrict__ offy,
                        const int* __restrict__ offx,
                        float* __restrict__ out)
{
    // Each thread produces a float4 = 4 adjacent output x-pixels.
    // quad index layout: (((cut*BATCH + b)*CHAN + c)*OUTS + y)*(OUTS/4) + xq
    const int XQ = OUTS / 4;  // 56
    long long idx = (long long)blockIdx.x * blockDim.x + threadIdx.x;

    int xq = (int)(idx % XQ);
    long long r = idx / XQ;
    int y = (int)(r % OUTS); r /= OUTS;
    int c = (int)(r % CHAN); r /= CHAN;
    int b = (int)(r % BATCH); r /= BATCH;
    int cut = (int)r;
    if (cut >= CUTN) return;

    const int sz = sizes[cut];
    const int oy = offy[cut];
    const int ox = offx[cut];

    // base of the crop inside plane (b,c)
    const float* plane = x + (((long long)(b * CHAN + c) * HW + oy) * HW + ox);

    // row bin (shared by the 4 pixels)
    const int sy = (y * sz) / OUTS;
    const int ey = ((y + 1) * sz + OUTS - 1) / OUTS;
    const int ny = ey - sy;

    float acc[4];
    #pragma unroll
    for (int k = 0; k < 4; k++) {
        const int xo = xq * 4 + k;
        const int sx = (xo * sz) / OUTS;
        const int ex = ((xo + 1) * sz + OUTS - 1) / OUTS;
        float s = 0.0f;
        for (int iy = sy; iy < ey; iy++) {
            const float* row = plane + (long long)iy * HW;
            for (int ix = sx; ix < ex; ix++) {
                s += __ldg(row + ix);
            }
        }
        acc[k] = s / (float)(ny * (ex - sx));
    }

    float4 res = make_float4(acc[0], acc[1], acc[2], acc[3]);
    reinterpret_cast<float4*>(out)[idx] = res;
}

extern "C" void kernel_launch(void* const* d_in, const int* in_sizes, int n_in,
                              void* d_out, int out_size)
{
    const float* x     = (const float*)d_in[0];
    const int*   sizes = (const int*)d_in[1];
    const int*   oy    = (const int*)d_in[2];
    const int*   ox    = (const int*)d_in[3];
    float* out = (float*)d_out;

    // total quads = CUTN*BATCH*CHAN*OUTS*(OUTS/4) = 9,633,792
    const long long quads = (long long)CUTN * BATCH * CHAN * OUTS * (OUTS / 4);
    const int threads = 256;
    const long long blocks = (quads + threads - 1) / threads;

    makecutouts_kernel<<<(unsigned)blocks, threads>>>(x, sizes, oy, ox, out);
}

// round 3
// speedup vs baseline: 1.0734x; 1.0734x over previous
#include <cuda_runtime.h>

// MakeCutouts: 32 cutouts of x[8,3,512,512] fp32, each adaptive-avg-pooled
// (torch bins) to 224x224. Output [32*8, 3, 224, 224] fp32.
//
// One block per output row (cut, b, c, y).
//   Phase 1: vertical sum of the ny (<=4) input rows of this y-bin into
//            shared colsum[sz] (coalesced, predicated unroll).
//   Phase 2: each of 224 threads sums nx (<=4) colsum entries -> one pixel.
// Bin width bound: sz/224 < 3  =>  ceil bins span at most 4 input pixels.

#define OUTS   224
#define BATCH  8
#define CHAN   3
#define HW     512
#define CUTN   32
#define NPLANE (BATCH * CHAN)   // 24

__global__ __launch_bounds__(256)
void makecutouts_rows(const float* __restrict__ x,
                      const int* __restrict__ sizes,
                      const int* __restrict__ offy,
                      const int* __restrict__ offx,
                      float* __restrict__ out)
{
    __shared__ float colsum[HW];

    const int tid = threadIdx.x;
    int bid = blockIdx.x;

    const int y     = bid % OUTS;  bid /= OUTS;
    const int plane = bid % NPLANE;       // b*CHAN + c
    const int cut   = bid / NPLANE;

    const int sz = __ldg(sizes + cut);
    const int oy = __ldg(offy + cut);
    const int ox = __ldg(offx + cut);

    // y-bin (divisions by constant 224 -> mul/shift)
    const int sy = (y * sz) / OUTS;
    const int ey = ((y + 1) * sz + (OUTS - 1)) / OUTS;
    const int ny = ey - sy;                  // 1..4

    // base of the first row of this y-bin inside plane (b,c)
    const float* rowp = x + (((long long)plane * HW) + (oy + sy)) * HW + ox;

    // Phase 1: vertical sum into shared (sz <= 512, 256 threads -> <=2 iters)
    #pragma unroll 2
    for (int col = tid; col < HW; col += 256) {
        if (col < sz) {
            float s = __ldg(rowp + col);
            if (ny > 1) s += __ldg(rowp + col + HW);
            if (ny > 2) s += __ldg(rowp + col + 2 * HW);
            if (ny > 3) s += __ldg(rowp + col + 3 * HW);
            colsum[col] = s;
        }
    }
    __syncthreads();

    // Phase 2: horizontal sum of <=4 entries, one pixel per thread
    if (tid < OUTS) {
        const int sx = (tid * sz) / OUTS;
        const int ex = ((tid + 1) * sz + (OUTS - 1)) / OUTS;
        const int nx = ex - sx;              // 1..4

        float s = colsum[sx];
        if (nx > 1) s += colsum[sx + 1];
        if (nx > 2) s += colsum[sx + 2];
        if (nx > 3) s += colsum[sx + 3];

        const float inv = __fdividef(1.0f, (float)(ny * nx));
        const long long oidx =
            ((long long)(cut * NPLANE + plane) * OUTS + y) * OUTS + tid;
        out[oidx] = s * inv;
    }
}

extern "C" void kernel_launch(void* const* d_in, const int* in_sizes, int n_in,
                              void* d_out, int out_size)
{
    const float* x     = (const float*)d_in[0];
    const int*   sizes = (const int*)d_in[1];
    const int*   oy    = (const int*)d_in[2];
    const int*   ox    = (const int*)d_in[3];
    float* out = (float*)d_out;

    const int blocks = CUTN * NPLANE * OUTS;   // 172032
    makecutouts_rows<<<blocks, 256>>>(x, sizes, oy, ox, out);
}

// round 4
// speedup vs baseline: 1.3077x; 1.2183x over previous
#include <cuda_runtime.h>

// MakeCutouts: 32 cutouts of x[8,3,512,512] fp32, adaptive-avg-pool (torch
// bins) to 224x224 each. Output [256, 3, 224, 224] fp32.
//
// Block = (cut, plane, ygroup of 28 output rows). Per row:
//   Phase 1: vertical sum of ny (<=4) input rows into shared colsum,
//            float4 loads (aligned-down from ox), packed f32x2 adds.
//   Phase 2: 224 threads each sum nx (<=4) shared floats -> one pixel.
// x-bin indices (sx, nx, invx) are row-invariant: computed once per block.

#define OUTS   224
#define BATCH  8
#define CHAN   3
#define HW     512
#define CUTN   32
#define NPLANE (BATCH * CHAN)   // 24
#define YG     28               // output rows per block
#define NYG    (OUTS / YG)      // 8

__device__ __forceinline__ void f4acc(float4& a, float4 b) {
    asm("{\n\t"
        ".reg .b64 t0, t1;\n\t"
        "mov.b64 t0, {%0, %1}; mov.b64 t1, {%4, %5};\n\t"
        "add.rn.f32x2 t0, t0, t1; mov.b64 {%0, %1}, t0;\n\t"
        "mov.b64 t0, {%2, %3}; mov.b64 t1, {%6, %7};\n\t"
        "add.rn.f32x2 t0, t0, t1; mov.b64 {%2, %3}, t0;\n\t"
        "}"
        : "+f"(a.x), "+f"(a.y), "+f"(a.z), "+f"(a.w)
        : "f"(b.x), "f"(b.y), "f"(b.z), "f"(b.w));
}

__device__ __forceinline__ float inv_small(int n) {
    // n in 1..4 -> 1/n via selects (no MUFU)
    return n == 1 ? 1.0f : (n == 2 ? 0.5f : (n == 3 ? (1.0f / 3.0f) : 0.25f));
}

__global__ __launch_bounds__(256)
void makecutouts_v3(const float* __restrict__ x,
                    const int* __restrict__ sizes,
                    const int* __restrict__ offy,
                    const int* __restrict__ offx,
                    float* __restrict__ out)
{
    __shared__ float buf[2][520];

    const int tid = threadIdx.x;
    int bid = blockIdx.x;
    const int yg    = bid % NYG;  bid /= NYG;
    const int plane = bid % NPLANE;
    const int cut   = bid / NPLANE;

    const int sz = __ldg(sizes + cut);
    const int oy = __ldg(offy + cut);
    const int ox = __ldg(offx + cut);

    const int ox_al = ox & ~3;
    const int shift = ox - ox_al;        // 0..3
    const int span  = shift + sz;        // columns to cover from ox_al
    const int nlanes = (span + 3) >> 2;  // <= 129 float4 lanes

    const float* pbase = x + (long long)plane * (HW * HW) + ox_al;

    // ---- row-invariant phase-2 setup ----
    int sx = 0, nx = 1;
    float invx = 1.0f;
    if (tid < OUTS) {
        sx = (tid * sz) / OUTS;
        const int ex = ((tid + 1) * sz + (OUTS - 1)) / OUTS;
        nx = ex - sx;                    // 1..4
        invx = inv_small(nx);
    }

    const int y0 = yg * YG;
    long long oidx = ((long long)(cut * NPLANE + plane) * OUTS + y0) * OUTS + tid;

    #pragma unroll 1
    for (int i = 0; i < YG; i++) {
        const int y  = y0 + i;
        const int sy = (y * sz) / OUTS;
        const int ey = ((y + 1) * sz + (OUTS - 1)) / OUTS;
        const int ny = ey - sy;          // 1..4

        float* cs = buf[i & 1];

        if (tid < nlanes) {
            const float* rp = pbase + (long long)(oy + sy) * HW + tid * 4;
            const int rem = span - tid * 4;   // > 0
            if (rem >= 4) {
                float4 a = __ldg((const float4*)rp);
                if (ny > 1) f4acc(a, __ldg((const float4*)(rp + HW)));
                if (ny > 2) f4acc(a, __ldg((const float4*)(rp + 2 * HW)));
                if (ny > 3) f4acc(a, __ldg((const float4*)(rp + 3 * HW)));
                *(float4*)(cs + tid * 4) = a;
            } else {
                // tail lane: 1..3 scalar columns (stay inside [ox, ox+sz))
                for (int k = 0; k < rem; k++) {
                    float s = __ldg(rp + k);
                    if (ny > 1) s += __ldg(rp + k + HW);
                    if (ny > 2) s += __ldg(rp + k + 2 * HW);
                    if (ny > 3) s += __ldg(rp + k + 3 * HW);
                    cs[tid * 4 + k] = s;
                }
            }
        }
        __syncthreads();

        if (tid < OUTS) {
            const float* p = cs + shift + sx;
            float s = p[0];
            if (nx > 1) s += p[1];
            if (nx > 2) s += p[2];
            if (nx > 3) s += p[3];
            out[oidx] = s * (invx * inv_small(ny));
        }
        oidx += OUTS;
    }
}

extern "C" void kernel_launch(void* const* d_in, const int* in_sizes, int n_in,
                              void* d_out, int out_size)
{
    const float* x     = (const float*)d_in[0];
    const int*   sizes = (const int*)d_in[1];
    const int*   oy    = (const int*)d_in[2];
    const int*   ox    = (const int*)d_in[3];
    float* out = (float*)d_out;

    const int blocks = CUTN * NPLANE * NYG;   // 6144
    makecutouts_v3<<<blocks, 256>>>(x, sizes, oy, ox, out);
}

// round 5
// speedup vs baseline: 1.5752x; 1.2045x over previous
#include <cuda_runtime.h>

// MakeCutouts: 32 cutouts of x[8,3,512,512] fp32, adaptive-avg-pool (torch
// bins) to 224x224 each. Output [256, 3, 224, 224] fp32.
//
// Block = (cut, plane, 16-row y-group). Single barrier per block:
//   Phase 1: vertical sums of ALL 16 rows into shared buf[16][516],
//            row-pairs: threads [0,128) even row, [128,256) odd row,
//            float4 loads aligned-down from ox, deep MLP across rows.
//   Phase 2: 224 threads x 16 rows, each sums nx (<=4) shared floats.
// Bins span <= 4 input pixels (sz/224 < 3).

#define OUTS   224
#define BATCH  8
#define CHAN   3
#define HW     512
#define CUTN   32
#define NPLANE (BATCH * CHAN)   // 24
#define YG     16               // output rows per block
#define NYG    (OUTS / YG)      // 14
#define CSTRIDE 516

__device__ __forceinline__ void f4acc(float4& a, float4 b) {
    asm("{\n\t"
        ".reg .b64 t0, t1;\n\t"
        "mov.b64 t0, {%0, %1}; mov.b64 t1, {%4, %5};\n\t"
        "add.rn.f32x2 t0, t0, t1; mov.b64 {%0, %1}, t0;\n\t"
        "mov.b64 t0, {%2, %3}; mov.b64 t1, {%6, %7};\n\t"
        "add.rn.f32x2 t0, t0, t1; mov.b64 {%2, %3}, t0;\n\t"
        "}"
        : "+f"(a.x), "+f"(a.y), "+f"(a.z), "+f"(a.w)
        : "f"(b.x), "f"(b.y), "f"(b.z), "f"(b.w));
}

__device__ __forceinline__ float inv_small(int n) {
    return n == 1 ? 1.0f : (n == 2 ? 0.5f : (n == 3 ? (1.0f / 3.0f) : 0.25f));
}

__global__ __launch_bounds__(256)
void makecutouts_v4(const float* __restrict__ x,
                    const int* __restrict__ sizes,
                    const int* __restrict__ offy,
                    const int* __restrict__ offx,
                    float* __restrict__ out)
{
    __shared__ float buf[YG][CSTRIDE];   // 33,024 B

    const int tid = threadIdx.x;
    int bid = blockIdx.x;
    const int yg    = bid % NYG;  bid /= NYG;
    const int plane = bid % NPLANE;
    const int cut   = bid / NPLANE;

    const int sz = __ldg(sizes + cut);
    const int oy = __ldg(offy + cut);
    const int ox = __ldg(offx + cut);

    const int ox_al = ox & ~3;
    const int shift = ox - ox_al;        // 0..3
    const int span  = shift + sz;        // <= 515

    const float* pbase = x + (long long)plane * (HW * HW) + ox_al;
    const int y0 = yg * YG;

    // ---- Phase 1: all 16 rows, one row-pair per iteration ----
    const int lane = tid & 127;
    const int half = tid >> 7;
    const int rem  = span - lane * 4;

    #pragma unroll 4
    for (int ip = 0; ip < YG / 2; ip++) {
        const int row = ip * 2 + half;
        const int y   = y0 + row;
        const int sy  = (y * sz) / OUTS;
        const int ny  = ((y + 1) * sz + (OUTS - 1)) / OUTS - sy;   // 1..4

        const float* rp = pbase + (long long)(oy + sy) * HW + lane * 4;
        float* cs = &buf[row][0];

        if (rem >= 4) {
            float4 a = __ldg((const float4*)rp);
            if (ny > 1) f4acc(a, __ldg((const float4*)(rp + HW)));
            if (ny > 2) f4acc(a, __ldg((const float4*)(rp + 2 * HW)));
            if (ny > 3) f4acc(a, __ldg((const float4*)(rp + 3 * HW)));
            *(float4*)(cs + lane * 4) = a;
            // columns beyond 512 (only when span > 512, lane 127 owns them)
            if (lane == 127 && span > 512) {
                #pragma unroll
                for (int c = 512; c < 515; c++) {
                    if (c < span) {
                        const float* q = pbase + (long long)(oy + sy) * HW + c;
                        float s = __ldg(q);
                        if (ny > 1) s += __ldg(q + HW);
                        if (ny > 2) s += __ldg(q + 2 * HW);
                        if (ny > 3) s += __ldg(q + 3 * HW);
                        cs[c] = s;
                    }
                }
            }
        } else if (rem > 0) {
            #pragma unroll
            for (int k = 0; k < 3; k++) {
                if (k < rem) {
                    float s = __ldg(rp + k);
                    if (ny > 1) s += __ldg(rp + k + HW);
                    if (ny > 2) s += __ldg(rp + k + 2 * HW);
                    if (ny > 3) s += __ldg(rp + k + 3 * HW);
                    cs[lane * 4 + k] = s;
                }
            }
        }
    }

    __syncthreads();

    // ---- Phase 2: 224 threads x 16 rows, no barriers ----
    if (tid < OUTS) {
        const int sx = (tid * sz) / OUTS;
        const int ex = ((tid + 1) * sz + (OUTS - 1)) / OUTS;
        const int nx = ex - sx;              // 1..4
        const float invx = inv_small(nx);
        const int off = shift + sx;

        long long oidx =
            ((long long)(cut * NPLANE + plane) * OUTS + y0) * OUTS + tid;

        #pragma unroll 4
        for (int i = 0; i < YG; i++) {
            const int y  = y0 + i;
            const int ny = ((y + 1) * sz + (OUTS - 1)) / OUTS - (y * sz) / OUTS;

            const float* p = &buf[i][off];
            float s = p[0];
            if (nx > 1) s += p[1];
            if (nx > 2) s += p[2];
            if (nx > 3) s += p[3];

            out[oidx] = s * (invx * inv_small(ny));
            oidx += OUTS;
        }
    }
}

extern "C" void kernel_launch(void* const* d_in, const int* in_sizes, int n_in,
                              void* d_out, int out_size)
{
    const float* x     = (const float*)d_in[0];
    const int*   sizes = (const int*)d_in[1];
    const int*   oy    = (const int*)d_in[2];
    const int*   ox    = (const int*)d_in[3];
    float* out = (float*)d_out;

    const int blocks = CUTN * NPLANE * NYG;   // 10752
    makecutouts_v4<<<blocks, 256>>>(x, sizes, oy, ox, out);
}

// round 6
// speedup vs baseline: 2.0819x; 1.3217x over previous
#include <cuda_runtime.h>

// MakeCutouts: 32 cutouts of x[8,3,512,512] fp32, adaptive-avg-pool (torch
// bins) to 224x224. Output [256, 3, 224, 224] fp32.
//
// Block = (cut, plane, 8-row y-group). smem 16.9KB -> 8 blocks/SM (100% occ).
//   Setup:   threads 0..7 compute per-row (sy, ny, 1/ny) into shared.
//   Phase 1: vertical sums of 8 rows into buf[8][516]; row-pairs
//            (threads [0,128) even row, [128,256) odd row), float4 loads.
//   Phase 2: 224 threads x 8 rows, each sums nx (<=4) shared floats.
// Bins span <= 4 input pixels (sz/224 < 3).

#define OUTS   224
#define BATCH  8
#define CHAN   3
#define HW     512
#define CUTN   32
#define NPLANE (BATCH * CHAN)   // 24
#define YG     8                // output rows per block
#define NYG    (OUTS / YG)      // 28
#define CSTRIDE 516

__device__ __forceinline__ void f4acc(float4& a, float4 b) {
    asm("{\n\t"
        ".reg .b64 t0, t1;\n\t"
        "mov.b64 t0, {%0, %1}; mov.b64 t1, {%4, %5};\n\t"
        "add.rn.f32x2 t0, t0, t1; mov.b64 {%0, %1}, t0;\n\t"
        "mov.b64 t0, {%2, %3}; mov.b64 t1, {%6, %7};\n\t"
        "add.rn.f32x2 t0, t0, t1; mov.b64 {%2, %3}, t0;\n\t"
        "}"
        : "+f"(a.x), "+f"(a.y), "+f"(a.z), "+f"(a.w)
        : "f"(b.x), "f"(b.y), "f"(b.z), "f"(b.w));
}

__device__ __forceinline__ float inv_small(int n) {
    return n == 1 ? 1.0f : (n == 2 ? 0.5f : (n == 3 ? (1.0f / 3.0f) : 0.25f));
}

__global__ __launch_bounds__(256)
void makecutouts_v5(const float* __restrict__ x,
                    const int* __restrict__ sizes,
                    const int* __restrict__ offy,
                    const int* __restrict__ offx,
                    float* __restrict__ out)
{
    __shared__ float buf[YG][CSTRIDE];   // 16,512 B
    __shared__ int   syny[YG];           // sy | ny<<16
    __shared__ float invy_sh[YG];

    const int tid = threadIdx.x;
    int bid = blockIdx.x;
    const int yg    = bid % NYG;  bid /= NYG;
    const int plane = bid % NPLANE;
    const int cut   = bid / NPLANE;

    const int sz = __ldg(sizes + cut);
    const int oy = __ldg(offy + cut);
    const int ox = __ldg(offx + cut);

    const int ox_al = ox & ~3;
    const int shift = ox - ox_al;        // 0..3
    const int span  = shift + sz;        // <= 515
    const int y0 = yg * YG;

    // ---- per-row metadata (once per block) ----
    if (tid < YG) {
        const int y  = y0 + tid;
        const int sy = (y * sz) / OUTS;
        const int ny = ((y + 1) * sz + (OUTS - 1)) / OUTS - sy;   // 1..4
        syny[tid]    = sy | (ny << 16);
        invy_sh[tid] = inv_small(ny);
    }

    const float* pbase = x + (long long)plane * (HW * HW) + ox_al;

    __syncthreads();

    // ---- Phase 1: 8 rows, one row-pair per iteration ----
    const int lane = tid & 127;
    const int half = tid >> 7;
    const int rem  = span - lane * 4;

    #pragma unroll
    for (int ip = 0; ip < YG / 2; ip++) {
        const int row = ip * 2 + half;
        const int m   = syny[row];
        const int sy  = m & 0xFFFF;
        const int ny  = m >> 16;

        const float* rp = pbase + (long long)(oy + sy) * HW + lane * 4;
        float* cs = &buf[row][0];

        if (rem >= 4) {
            float4 a = __ldg((const float4*)rp);
            if (ny > 1) f4acc(a, __ldg((const float4*)(rp + HW)));
            if (ny > 2) f4acc(a, __ldg((const float4*)(rp + 2 * HW)));
            if (ny > 3) f4acc(a, __ldg((const float4*)(rp + 3 * HW)));
            *(float4*)(cs + lane * 4) = a;
            if (lane == 127 && span > 512) {
                #pragma unroll
                for (int c = 512; c < 515; c++) {
                    if (c < span) {
                        const float* q = pbase + (long long)(oy + sy) * HW + c;
                        float s = __ldg(q);
                        if (ny > 1) s += __ldg(q + HW);
                        if (ny > 2) s += __ldg(q + 2 * HW);
                        if (ny > 3) s += __ldg(q + 3 * HW);
                        cs[c] = s;
                    }
                }
            }
        } else if (rem > 0) {
            #pragma unroll
            for (int k = 0; k < 3; k++) {
                if (k < rem) {
                    float s = __ldg(rp + k);
                    if (ny > 1) s += __ldg(rp + k + HW);
                    if (ny > 2) s += __ldg(rp + k + 2 * HW);
                    if (ny > 3) s += __ldg(rp + k + 3 * HW);
                    cs[lane * 4 + k] = s;
                }
            }
        }
    }

    __syncthreads();

    // ---- Phase 2: 224 threads x 8 rows, no barriers ----
    if (tid < OUTS) {
        const int sx = (tid * sz) / OUTS;
        const int ex = ((tid + 1) * sz + (OUTS - 1)) / OUTS;
        const int nx = ex - sx;              // 1..4
        const float invx = inv_small(nx);
        const int off = shift + sx;

        long long oidx =
            ((long long)(cut * NPLANE + plane) * OUTS + y0) * OUTS + tid;

        #pragma unroll
        for (int i = 0; i < YG; i++) {
            const float* p = &buf[i][off];
            float s = p[0];
            if (nx > 1) s += p[1];
            if (nx > 2) s += p[2];
            if (nx > 3) s += p[3];

            out[oidx] = s * (invx * invy_sh[i]);
            oidx += OUTS;
        }
    }
}

extern "C" void kernel_launch(void* const* d_in, const int* in_sizes, int n_in,
                              void* d_out, int out_size)
{
    const float* x     = (const float*)d_in[0];
    const int*   sizes = (const int*)d_in[1];
    const int*   oy    = (const int*)d_in[2];
    const int*   ox    = (const int*)d_in[3];
    float* out = (float*)d_out;

    const int blocks = CUTN * NPLANE * NYG;   // 21504
    makecutouts_v5<<<blocks, 256>>>(x, sizes, oy, ox, out);
}